// round 4
// baseline (speedup 1.0000x reference)
#include <cuda_runtime.h>
#include <math.h>

// Problem constants (fixed by the reference)
#define N_BAGS   64
#define GRID_W   96
#define NCELLS   (N_BAGS * GRID_W * GRID_W)   // 589824 (divisible by 4)
#define CAP      16                            // bucket capacity; Poisson(0.222) => overflow ~impossible
#define NQ       512
#define NMEM     131072
#define DIM      256

// Scratch: device globals (no runtime allocation allowed).
// Byte counters packed 4-per-word so pass 1 can use a byte-lane atomicAdd.
__device__ unsigned int g_cnt32[NCELLS / 4];
__device__ int          g_cell_items[NCELLS * CAP];

// ---------------------------------------------------------------------------
// Pass 1: scatter memory-row indices into (bag, y, x) cells.
// Byte-lane atomicAdd: old byte value = slot index for this row.
// ---------------------------------------------------------------------------
__global__ void count_kernel(const int* __restrict__ bag_idxs,
                             const int* __restrict__ xs,
                             const int* __restrict__ ys) {
    int n = blockIdx.x * blockDim.x + threadIdx.x;
    if (n >= NMEM) return;
    int cell = (bag_idxs[n] * GRID_W + ys[n]) * GRID_W + xs[n];
    unsigned shift = (cell & 3) * 8;
    unsigned old = atomicAdd(&g_cnt32[cell >> 2], 1u << shift);
    int slot = (old >> shift) & 0xFF;
    if (slot < CAP) g_cell_items[cell * CAP + slot] = n;
}

// ---------------------------------------------------------------------------
// Pass 2: one warp per query, restructured for MLP.
//   lanes 0..7 each own one neighbor cell -> 8 parallel count loads
//   -> warp prefix sum -> parallel item loads into shared candidate list
//   -> candidates processed two at a time (pipelined row loads).
// ---------------------------------------------------------------------------
__global__ void query_kernel(const float* __restrict__ q,
                             const float* __restrict__ memory,
                             const int* __restrict__ bag_idx,
                             const int* __restrict__ xc,
                             const int* __restrict__ yc,
                             float* __restrict__ out) {
    __shared__ int s_cand[4][8 * CAP];          // per-warp candidate lists
    const unsigned FULL = 0xFFFFFFFFu;

    int wl   = threadIdx.x >> 5;                // warp within block (0..3)
    int warp = blockIdx.x * 4 + wl;             // query index
    int lane = threadIdx.x & 31;
    if (warp >= NQ) return;

    // ---- query row: each lane holds 8 consecutive elements (2 x float4) ----
    const float* qrow = q + warp * DIM + lane * 8;
    float4 a = *(const float4*)(qrow);
    float4 b = *(const float4*)(qrow + 4);

    int bag = bag_idx[warp];
    int x0  = xc[warp];
    int y0  = yc[warp];

    // ---- lanes 0..7: probe the 8 neighbor cells in parallel ----
    // neighbor index: idx = lane + (lane >= 4), skipping the center (0,0)
    int cnt = 0;
    int cell = 0;
    if (lane < 8) {
        int idx = lane + (lane >= 4 ? 1 : 0);   // 0..8 minus 4
        int dx = idx % 3 - 1;
        int dy = idx / 3 - 1;
        int x = x0 + dx, y = y0 + dy;
        if (x >= 0 && x < GRID_W && y >= 0 && y < GRID_W) {
            cell = (bag * GRID_W + y) * GRID_W + x;
            const unsigned char* cnt8 = (const unsigned char*)g_cnt32;
            int c = cnt8[cell];
            cnt = c < CAP ? c : CAP;
        }
    }

    // ---- ||q||^2 warp reduce (overlaps with the scatter below) ----
    float ss = a.x * a.x + a.y * a.y + a.z * a.z + a.w * a.w
             + b.x * b.x + b.y * b.y + b.z * b.z + b.w * b.w;
    #pragma unroll
    for (int o = 16; o; o >>= 1) ss += __shfl_xor_sync(FULL, ss, o);
    float inv = rsqrtf(ss) * 5.0f;              // 1 / (||q|| * 0.2)

    // ---- exclusive prefix sum of counts over lanes 0..7 ----
    int off = cnt;
    #pragma unroll
    for (int d = 1; d < 8; d <<= 1) {
        int v = __shfl_up_sync(FULL, off, d);
        if (lane >= d) off += v;
    }
    int total  = __shfl_sync(FULL, off, 7);     // inclusive sum at lane 7
    int my_off = off - cnt;

    // ---- parallel item loads into the shared candidate list ----
    if (lane < 8) {
        #pragma unroll 4
        for (int i = 0; i < cnt; i++)
            s_cand[wl][my_off + i] = g_cell_items[cell * CAP + i];
    }
    __syncwarp();

    // ---- process candidates two at a time (overlap DRAM row fetches) ----
    float s = 0.0f;
    for (int c = 0; c < total; c += 2) {
        int n0 = s_cand[wl][c];
        bool has1 = (c + 1) < total;
        int n1 = has1 ? s_cand[wl][c + 1] : n0;

        const float* r0 = memory + (size_t)n0 * DIM + lane * 8;
        const float* r1 = memory + (size_t)n1 * DIM + lane * 8;
        float4 p0 = *(const float4*)(r0);
        float4 p1 = *(const float4*)(r0 + 4);
        float4 t0 = *(const float4*)(r1);
        float4 t1 = *(const float4*)(r1 + 4);

        float d0 = a.x * p0.x + a.y * p0.y + a.z * p0.z + a.w * p0.w
                 + b.x * p1.x + b.y * p1.y + b.z * p1.z + b.w * p1.w;
        float d1 = a.x * t0.x + a.y * t0.y + a.z * t0.z + a.w * t0.w
                 + b.x * t1.x + b.y * t1.y + b.z * t1.z + b.w * t1.w;

        #pragma unroll
        for (int o = 16; o; o >>= 1) {          // interleaved reductions
            d0 += __shfl_xor_sync(FULL, d0, o);
            d1 += __shfl_xor_sync(FULL, d1, o);
        }
        s += expf(d0 * inv);
        if (has1) s += expf(d1 * inv);
    }
    if (lane == 0) out[warp] = s;
}

extern "C" void kernel_launch(void* const* d_in, const int* in_sizes, int n_in,
                              void* d_out, int out_size) {
    const float* q        = (const float*)d_in[0];   // [512, 256]
    const float* memory   = (const float*)d_in[1];   // [131072, 256]
    const int*   bag_idx  = (const int*)d_in[2];     // [512]
    const int*   x_coord  = (const int*)d_in[3];     // [512]
    const int*   y_coord  = (const int*)d_in[4];     // [512]
    const int*   bag_idxs = (const int*)d_in[5];     // [131072]
    const int*   x_coords = (const int*)d_in[6];     // [131072]
    const int*   y_coords = (const int*)d_in[7];     // [131072]
    float* out = (float*)d_out;                      // [512]

    // Zero the byte counters (0.59 MB, graph-capturable async memset).
    void* cnt_ptr = nullptr;
    cudaGetSymbolAddress(&cnt_ptr, g_cnt32);
    cudaMemsetAsync(cnt_ptr, 0, NCELLS);

    // Pass 1: bucket memory rows by (bag, y, x).
    count_kernel<<<(NMEM + 255) / 256, 256>>>(bag_idxs, x_coords, y_coords);

    // Pass 2: one warp per query; 512 warps total, 4 per block.
    query_kernel<<<NQ / 4, 128>>>(q, memory, bag_idx, x_coord, y_coord, out);
}

// round 5
// speedup vs baseline: 1.3708x; 1.3708x over previous
#include <cuda_runtime.h>
#include <math.h>

// Problem constants (fixed by the reference)
#define N_BAGS   64
#define GRID_W   96
#define NCELLS   (N_BAGS * GRID_W * GRID_W)   // 589824
#define CAP      16                            // bucket capacity; Poisson(0.222) => overflow ~impossible
#define NQ       512
#define NMEM     131072
#define DIM      256

// Scratch: device globals (no runtime allocation allowed).
// NOTE: counters are NOT fully memset each call. Only the <=4096 cells that
// queries actually probe are zeroed (pass 0). Never-probed cells accumulate
// garbage across graph replays — harmless: they are never read, and item
// writes are guarded by slot < CAP.
__device__ int g_cell_count[NCELLS];
__device__ int g_cell_items[NCELLS * CAP];

__device__ __forceinline__ int neighbor_cell(int bag, int x0, int y0, int nb,
                                             bool& valid) {
    int idx = nb + (nb >= 4 ? 1 : 0);          // 0..8 skipping center (4)
    int dx = idx % 3 - 1;
    int dy = idx / 3 - 1;
    int x = x0 + dx, y = y0 + dy;
    valid = (x >= 0) & (x < GRID_W) & (y >= 0) & (y < GRID_W);
    return (bag * GRID_W + y) * GRID_W + x;
}

// ---------------------------------------------------------------------------
// Pass 0: zero exactly the cells that pass 2 will read, plus the output.
// One thread per (query, neighbor): 4096 threads total.
// ---------------------------------------------------------------------------
__global__ void zero_kernel(const int* __restrict__ bag_idx,
                            const int* __restrict__ xc,
                            const int* __restrict__ yc,
                            float* __restrict__ out) {
    int tid = blockIdx.x * blockDim.x + threadIdx.x;
    if (tid < NQ) out[tid] = 0.0f;
    if (tid >= NQ * 8) return;
    int qi = tid >> 3, nb = tid & 7;
    bool valid;
    int cell = neighbor_cell(bag_idx[qi], xc[qi], yc[qi], nb, valid);
    if (valid) g_cell_count[cell] = 0;
}

// ---------------------------------------------------------------------------
// Pass 1: scatter memory-row indices into (bag, y, x) cells.
// Plain 32-bit spread atomics (round-3 evidence: ~1us).
// ---------------------------------------------------------------------------
__global__ void count_kernel(const int* __restrict__ bag_idxs,
                             const int* __restrict__ xs,
                             const int* __restrict__ ys) {
    int n = blockIdx.x * blockDim.x + threadIdx.x;
    if (n >= NMEM) return;
    int cell = (bag_idxs[n] * GRID_W + ys[n]) * GRID_W + xs[n];
    int slot = atomicAdd(&g_cell_count[cell], 1);
    if (slot < CAP) g_cell_items[cell * CAP + slot] = n;
}

// ---------------------------------------------------------------------------
// Pass 2: one warp per (query, neighbor-cell) -> 4096 warps.
// Candidates within the cell processed 4 rows at a time (pipelined DRAM
// fetches + interleaved reductions). Partial sums combined with atomicAdd.
// ---------------------------------------------------------------------------
__global__ void query_kernel(const float* __restrict__ q,
                             const float* __restrict__ memory,
                             const int* __restrict__ bag_idx,
                             const int* __restrict__ xc,
                             const int* __restrict__ yc,
                             float* __restrict__ out) {
    const unsigned FULL = 0xFFFFFFFFu;
    int gw = blockIdx.x * (blockDim.x >> 5) + (threadIdx.x >> 5);
    if (gw >= NQ * 8) return;
    int qi   = gw >> 3;
    int nb   = gw & 7;
    int lane = threadIdx.x & 31;

    // Issue the query-row load early so it overlaps the probe chain.
    const float* qrow = q + qi * DIM + lane * 8;
    float4 a = *(const float4*)(qrow);
    float4 b = *(const float4*)(qrow + 4);

    bool valid;
    int cell = neighbor_cell(bag_idx[qi], xc[qi], yc[qi], nb, valid);
    if (!valid) return;

    int cnt = g_cell_count[cell];
    if (cnt > CAP) cnt = CAP;
    if (cnt == 0) return;

    // All item loads in parallel: lane i holds item i.
    int item = (lane < cnt) ? g_cell_items[cell * CAP + lane] : 0;

    // ||q||^2 warp reduce (independent work, overlaps the loads above).
    float ss = a.x * a.x + a.y * a.y + a.z * a.z + a.w * a.w
             + b.x * b.x + b.y * b.y + b.z * b.z + b.w * b.w;
    #pragma unroll
    for (int o = 16; o; o >>= 1) ss += __shfl_xor_sync(FULL, ss, o);
    float inv = rsqrtf(ss) * 5.0f;              // 1 / (||q|| * 0.2)

    float s = 0.0f;
    for (int c0 = 0; c0 < cnt; c0 += 4) {
        int k = cnt - c0; if (k > 4) k = 4;
        float d[4];
        #pragma unroll
        for (int j = 0; j < 4; j++) {
            int ci = c0 + j; if (ci >= cnt) ci = cnt - 1;   // dup last (cheap, cached)
            int n = __shfl_sync(FULL, item, ci);
            const float* mr = memory + (size_t)n * DIM + lane * 8;
            float4 m0 = *(const float4*)(mr);
            float4 m1 = *(const float4*)(mr + 4);
            d[j] = a.x * m0.x + a.y * m0.y + a.z * m0.z + a.w * m0.w
                 + b.x * m1.x + b.y * m1.y + b.z * m1.z + b.w * m1.w;
        }
        #pragma unroll
        for (int o = 16; o; o >>= 1) {          // 4 interleaved reductions
            d[0] += __shfl_xor_sync(FULL, d[0], o);
            d[1] += __shfl_xor_sync(FULL, d[1], o);
            d[2] += __shfl_xor_sync(FULL, d[2], o);
            d[3] += __shfl_xor_sync(FULL, d[3], o);
        }
        #pragma unroll
        for (int j = 0; j < 4; j++)
            if (j < k) s += expf(d[j] * inv);
    }
    if (lane == 0) atomicAdd(&out[qi], s);
}

extern "C" void kernel_launch(void* const* d_in, const int* in_sizes, int n_in,
                              void* d_out, int out_size) {
    const float* q        = (const float*)d_in[0];   // [512, 256]
    const float* memory   = (const float*)d_in[1];   // [131072, 256]
    const int*   bag_idx  = (const int*)d_in[2];     // [512]
    const int*   x_coord  = (const int*)d_in[3];     // [512]
    const int*   y_coord  = (const int*)d_in[4];     // [512]
    const int*   bag_idxs = (const int*)d_in[5];     // [131072]
    const int*   x_coords = (const int*)d_in[6];     // [131072]
    const int*   y_coords = (const int*)d_in[7];     // [131072]
    float* out = (float*)d_out;                      // [512]

    // Pass 0: zero probed counters + output (16 blocks).
    zero_kernel<<<(NQ * 8 + 255) / 256, 256>>>(bag_idx, x_coord, y_coord, out);

    // Pass 1: bucket memory rows by (bag, y, x).
    count_kernel<<<(NMEM + 255) / 256, 256>>>(bag_idxs, x_coords, y_coords);

    // Pass 2: one warp per (query, neighbor) = 4096 warps, 8 warps/block.
    query_kernel<<<(NQ * 8) / 8, 256>>>(q, memory, bag_idx, x_coord, y_coord, out);
}

// round 6
// speedup vs baseline: 1.3884x; 1.0129x over previous
#include <cuda_runtime.h>
#include <math.h>

// Problem constants (fixed by the reference)
#define N_BAGS   64
#define GRID_W   96
#define NCELLS   (N_BAGS * GRID_W * GRID_W)   // 589824
#define CAP      16                            // bucket capacity; Poisson(0.222) => overflow ~impossible
#define NQ       512
#define NMEM     131072
#define DIM      256

// Scratch: device globals (no runtime allocation allowed).
__device__ int g_cell_count[NCELLS];
__device__ int g_cell_items[NCELLS * CAP];

__device__ __forceinline__ int neighbor_cell(int bag, int x0, int y0, int nb,
                                             bool& valid) {
    int idx = nb + (nb >= 4 ? 1 : 0);          // 0..8 skipping center (4)
    int dx = idx % 3 - 1;
    int dy = idx / 3 - 1;
    int x = x0 + dx, y = y0 + dy;
    valid = (x >= 0) & (x < GRID_W) & (y >= 0) & (y < GRID_W);
    return (bag * GRID_W + y) * GRID_W + x;
}

// ---------------------------------------------------------------------------
// Pass 1: scatter memory-row indices into (bag, y, x) cells.
// Plain 32-bit spread atomics (round-3 evidence: memset+this ~1.5us total).
// Also zeroes the 512-float output (ordered before query by stream order).
// ---------------------------------------------------------------------------
__global__ void count_kernel(const int* __restrict__ bag_idxs,
                             const int* __restrict__ xs,
                             const int* __restrict__ ys,
                             float* __restrict__ out) {
    int n = blockIdx.x * blockDim.x + threadIdx.x;
    if (n < NQ) out[n] = 0.0f;
    if (n >= NMEM) return;
    int cell = (bag_idxs[n] * GRID_W + ys[n]) * GRID_W + xs[n];
    int slot = atomicAdd(&g_cell_count[cell], 1);
    if (slot < CAP) g_cell_items[cell * CAP + slot] = n;
}

// ---------------------------------------------------------------------------
// Pass 2: one warp per (query, neighbor-cell) -> 4096 warps.
// Candidates within the cell processed 4 rows at a time (pipelined DRAM
// fetches + interleaved reductions). Partial sums combined with atomicAdd.
// ---------------------------------------------------------------------------
__global__ void query_kernel(const float* __restrict__ q,
                             const float* __restrict__ memory,
                             const int* __restrict__ bag_idx,
                             const int* __restrict__ xc,
                             const int* __restrict__ yc,
                             float* __restrict__ out) {
    const unsigned FULL = 0xFFFFFFFFu;
    int gw = blockIdx.x * (blockDim.x >> 5) + (threadIdx.x >> 5);
    if (gw >= NQ * 8) return;
    int qi   = gw >> 3;
    int nb   = gw & 7;
    int lane = threadIdx.x & 31;

    // Issue the query-row load early so it overlaps the probe chain.
    const float* qrow = q + qi * DIM + lane * 8;
    float4 a = *(const float4*)(qrow);
    float4 b = *(const float4*)(qrow + 4);

    bool valid;
    int cell = neighbor_cell(bag_idx[qi], xc[qi], yc[qi], nb, valid);
    if (!valid) return;

    int cnt = g_cell_count[cell];
    if (cnt > CAP) cnt = CAP;
    if (cnt == 0) return;

    // All item loads in parallel: lane i holds item i.
    int item = (lane < cnt) ? g_cell_items[cell * CAP + lane] : 0;

    // ||q||^2 warp reduce (independent work, overlaps the loads above).
    float ss = a.x * a.x + a.y * a.y + a.z * a.z + a.w * a.w
             + b.x * b.x + b.y * b.y + b.z * b.z + b.w * b.w;
    #pragma unroll
    for (int o = 16; o; o >>= 1) ss += __shfl_xor_sync(FULL, ss, o);
    float inv = rsqrtf(ss) * 5.0f;              // 1 / (||q|| * 0.2)

    float s = 0.0f;
    for (int c0 = 0; c0 < cnt; c0 += 4) {
        int k = cnt - c0; if (k > 4) k = 4;
        float d[4];
        #pragma unroll
        for (int j = 0; j < 4; j++) {
            int ci = c0 + j; if (ci >= cnt) ci = cnt - 1;   // dup last (cheap, cached)
            int n = __shfl_sync(FULL, item, ci);
            const float* mr = memory + (size_t)n * DIM + lane * 8;
            float4 m0 = *(const float4*)(mr);
            float4 m1 = *(const float4*)(mr + 4);
            d[j] = a.x * m0.x + a.y * m0.y + a.z * m0.z + a.w * m0.w
                 + b.x * m1.x + b.y * m1.y + b.z * m1.z + b.w * m1.w;
        }
        #pragma unroll
        for (int o = 16; o; o >>= 1) {          // 4 interleaved reductions
            d[0] += __shfl_xor_sync(FULL, d[0], o);
            d[1] += __shfl_xor_sync(FULL, d[1], o);
            d[2] += __shfl_xor_sync(FULL, d[2], o);
            d[3] += __shfl_xor_sync(FULL, d[3], o);
        }
        #pragma unroll
        for (int j = 0; j < 4; j++)
            if (j < k) s += expf(d[j] * inv);
    }
    if (lane == 0) atomicAdd(&out[qi], s);
}

extern "C" void kernel_launch(void* const* d_in, const int* in_sizes, int n_in,
                              void* d_out, int out_size) {
    const float* q        = (const float*)d_in[0];   // [512, 256]
    const float* memory   = (const float*)d_in[1];   // [131072, 256]
    const int*   bag_idx  = (const int*)d_in[2];     // [512]
    const int*   x_coord  = (const int*)d_in[3];     // [512]
    const int*   y_coord  = (const int*)d_in[4];     // [512]
    const int*   bag_idxs = (const int*)d_in[5];     // [131072]
    const int*   x_coords = (const int*)d_in[6];     // [131072]
    const int*   y_coords = (const int*)d_in[7];     // [131072]
    float* out = (float*)d_out;                      // [512]

    // Zero the cell counters via DMA memset (round-3 evidence: cheap).
    void* cnt_ptr = nullptr;
    cudaGetSymbolAddress(&cnt_ptr, g_cell_count);
    cudaMemsetAsync(cnt_ptr, 0, NCELLS * sizeof(int));

    // Pass 1: bucket memory rows by (bag, y, x); also zeroes out[].
    count_kernel<<<(NMEM + 255) / 256, 256>>>(bag_idxs, x_coords, y_coords, out);

    // Pass 2: one warp per (query, neighbor) = 4096 warps, 8 warps/block.
    query_kernel<<<(NQ * 8) / 8, 256>>>(q, memory, bag_idx, x_coord, y_coord, out);
}

// round 7
// speedup vs baseline: 1.4189x; 1.0219x over previous
#include <cuda_runtime.h>
#include <math.h>

// Problem constants (fixed by the reference)
#define N_BAGS   64
#define GRID_W   96
#define NCELLS   (N_BAGS * GRID_W * GRID_W)   // 589824
#define CAP      16        // bucket capacity; Poisson(0.222) => overflow ~impossible
#define NQ       512
#define NMEM     131072
#define DIM      256

#define NBLK     128
#define NTHR     512
#define NTASK    (NQ * 8)                      // 4096 (query, neighbor) tasks

// Scratch: device globals (no runtime allocation allowed).
// Counters are NOT fully zeroed: phase 0 zeroes only the <=4096 probed cells.
// Unprobed cells accumulate garbage across graph replays — harmless: never
// read, and item writes are guarded by slot < CAP (int wrap is benign).
__device__ int g_cell_count[NCELLS];
__device__ int g_cell_items[NCELLS * CAP];

// ---- software grid barrier (all 128 CTAs co-resident by construction) ----
__device__ unsigned          g_bar_cnt[2];
__device__ volatile unsigned g_bar_gen[2];

__device__ __forceinline__ void grid_sync(int id) {
    __syncthreads();
    if (threadIdx.x == 0) {
        __threadfence();
        unsigned gen = g_bar_gen[id];
        if (atomicAdd(&g_bar_cnt[id], 1u) == (unsigned)(gridDim.x - 1)) {
            g_bar_cnt[id] = 0;
            __threadfence();
            g_bar_gen[id] = gen + 1;           // release
        } else {
            while (g_bar_gen[id] == gen) { }   // spin (volatile load)
        }
        __threadfence();
    }
    __syncthreads();
}

__device__ __forceinline__ int neighbor_cell(int bag, int x0, int y0, int nb,
                                             bool& valid) {
    int idx = nb + (nb >= 4 ? 1 : 0);          // 0..8 skipping center (4)
    int dx = idx % 3 - 1;
    int dy = idx / 3 - 1;
    int x = x0 + dx, y = y0 + dy;
    valid = (x >= 0) & (x < GRID_W) & (y >= 0) & (y < GRID_W);
    return (bag * GRID_W + y) * GRID_W + x;
}

// ---------------------------------------------------------------------------
// Single fused kernel: P0 targeted-zero -> barrier -> P1 scatter -> barrier
// -> P2 query. One graph node, no memset.
// ---------------------------------------------------------------------------
__global__ void __launch_bounds__(NTHR, 1)
fused_kernel(const float* __restrict__ q,
             const float* __restrict__ memory,
             const int*   __restrict__ bag_idx,
             const int*   __restrict__ xc,
             const int*   __restrict__ yc,
             const int*   __restrict__ bag_idxs,
             const int*   __restrict__ xs,
             const int*   __restrict__ ys,
             float*       __restrict__ out) {
    const unsigned FULL = 0xFFFFFFFFu;
    int tid = blockIdx.x * NTHR + threadIdx.x;           // 0 .. 65535

    // ---- Phase 0: zero exactly the probed cell counters + output ----
    if (tid < NQ) out[tid] = 0.0f;
    if (tid < NTASK) {
        int qi = tid >> 3, nb = tid & 7;
        bool valid;
        int cell = neighbor_cell(bag_idx[qi], xc[qi], yc[qi], nb, valid);
        if (valid) g_cell_count[cell] = 0;
    }
    grid_sync(0);

    // ---- Phase 1: scatter memory rows into (bag, y, x) cells ----
    #pragma unroll
    for (int r = 0; r < 2; r++) {
        int n = tid + r * (NBLK * NTHR);
        if (n < NMEM) {
            int cell = (bag_idxs[n] * GRID_W + ys[n]) * GRID_W + xs[n];
            int slot = atomicAdd(&g_cell_count[cell], 1);
            if (slot < CAP) g_cell_items[cell * CAP + slot] = n;
        }
    }
    grid_sync(1);

    // ---- Phase 2: one warp per (query, neighbor-cell) task ----
    int warp = tid >> 5;                                  // 0 .. 2047
    int lane = threadIdx.x & 31;
    const int nwarps = NBLK * NTHR / 32;                  // 2048

    for (int task = warp; task < NTASK; task += nwarps) {
        int qi = task >> 3;
        int nb = task & 7;

        // Issue the query-row load early so it overlaps the probe chain.
        const float* qrow = q + qi * DIM + lane * 8;
        float4 a = *(const float4*)(qrow);
        float4 b = *(const float4*)(qrow + 4);

        bool valid;
        int cell = neighbor_cell(bag_idx[qi], xc[qi], yc[qi], nb, valid);
        if (!valid) continue;

        int cnt = g_cell_count[cell];
        if (cnt > CAP) cnt = CAP;
        if (cnt == 0) continue;

        // All item loads in parallel: lane i holds item i.
        int item = (lane < cnt) ? g_cell_items[cell * CAP + lane] : 0;

        // ||q||^2 warp reduce (overlaps the loads above).
        float ss = a.x * a.x + a.y * a.y + a.z * a.z + a.w * a.w
                 + b.x * b.x + b.y * b.y + b.z * b.z + b.w * b.w;
        #pragma unroll
        for (int o = 16; o; o >>= 1) ss += __shfl_xor_sync(FULL, ss, o);
        float inv = rsqrtf(ss) * 5.0f;                    // 1 / (||q|| * 0.2)

        float s = 0.0f;
        for (int c0 = 0; c0 < cnt; c0 += 4) {
            int k = cnt - c0; if (k > 4) k = 4;
            float d[4];
            #pragma unroll
            for (int j = 0; j < 4; j++) {
                int ci = c0 + j; if (ci >= cnt) ci = cnt - 1;  // dup last (cached)
                int n = __shfl_sync(FULL, item, ci);
                const float* mr = memory + (size_t)n * DIM + lane * 8;
                float4 m0 = *(const float4*)(mr);
                float4 m1 = *(const float4*)(mr + 4);
                d[j] = a.x * m0.x + a.y * m0.y + a.z * m0.z + a.w * m0.w
                     + b.x * m1.x + b.y * m1.y + b.z * m1.z + b.w * m1.w;
            }
            #pragma unroll
            for (int o = 16; o; o >>= 1) {                 // 4 interleaved reductions
                d[0] += __shfl_xor_sync(FULL, d[0], o);
                d[1] += __shfl_xor_sync(FULL, d[1], o);
                d[2] += __shfl_xor_sync(FULL, d[2], o);
                d[3] += __shfl_xor_sync(FULL, d[3], o);
            }
            #pragma unroll
            for (int j = 0; j < 4; j++)
                if (j < k) s += expf(d[j] * inv);
        }
        if (lane == 0) atomicAdd(&out[qi], s);
    }
}

extern "C" void kernel_launch(void* const* d_in, const int* in_sizes, int n_in,
                              void* d_out, int out_size) {
    const float* q        = (const float*)d_in[0];   // [512, 256]
    const float* memory   = (const float*)d_in[1];   // [131072, 256]
    const int*   bag_idx  = (const int*)d_in[2];     // [512]
    const int*   x_coord  = (const int*)d_in[3];     // [512]
    const int*   y_coord  = (const int*)d_in[4];     // [512]
    const int*   bag_idxs = (const int*)d_in[5];     // [131072]
    const int*   x_coords = (const int*)d_in[6];     // [131072]
    const int*   y_coords = (const int*)d_in[7];     // [131072]
    float* out = (float*)d_out;                      // [512]

    fused_kernel<<<NBLK, NTHR>>>(q, memory, bag_idx, x_coord, y_coord,
                                 bag_idxs, x_coords, y_coords, out);
}